// round 9
// baseline (speedup 1.0000x reference)
#include <cuda_runtime.h>
#include <stdint.h>

#define NN    8192
#define NT    256
#define NB    (NN / NT)     // 32 blocks
#define CHUNK 4096          // candidate buffer capacity per pass (2 passes)

// Threefry-2x32-20, key=(0,42), partitionable path: counter=(hi32,lo32)=(0,i),
// 32-bit output = o1 ^ o2.
__device__ __forceinline__ uint32_t threefry_bits_partitionable(uint32_t i)
{
    const uint32_t ks0 = 0u;
    const uint32_t ks1 = 42u;
    const uint32_t ks2 = 0x1BD11BDAu ^ ks0 ^ ks1;
    uint32_t x0 = 0u + ks0;
    uint32_t x1 = i  + ks1;
    #define TF_RND(r) { x0 += x1; x1 = (x1 << (r)) | (x1 >> (32 - (r))); x1 ^= x0; }
    TF_RND(13) TF_RND(15) TF_RND(26) TF_RND(6)
    x0 += ks1; x1 += ks2 + 1u;
    TF_RND(17) TF_RND(29) TF_RND(16) TF_RND(24)
    x0 += ks2; x1 += ks0 + 2u;
    TF_RND(13) TF_RND(15) TF_RND(26) TF_RND(6)
    x0 += ks0; x1 += ks1 + 3u;
    TF_RND(17) TF_RND(29) TF_RND(16) TF_RND(24)
    x0 += ks1; x1 += ks2 + 4u;
    TF_RND(13) TF_RND(15) TF_RND(26) TF_RND(6)
    x0 += ks2; x1 += ks0 + 5u;
    #undef TF_RND
    return x0 ^ x1;
}

// Single fused kernel, thread-per-row.
// Phase 1: block cooperatively screens all NN columns for possibly-nonzero eps
//          (certain-zero fast test; full eval only for survivors), compacting
//          candidates into shared memory in chunks.
// Phase 2: per-thread accumulate I_syn over candidates (skipped when none).
// Phase 3: coalesced elementwise epilogue (theta, v_next, lambda, threefry
//          bernoulli, outputs).
__global__ void __launch_bounds__(NT) k_fused(
        const float* __restrict__ w,
        const float* __restrict__ v,
        const float* __restrict__ I_ext,
        const float* __restrict__ E_L,
        const float* __restrict__ tau_m,
        const float* __restrict__ ts,
        const float* __restrict__ c,
        const float* __restrict__ Delta_u,
        const float* __restrict__ theta_v,
        const float* __restrict__ theta_inf,
        const float* __restrict__ J_theta,
        const float* __restrict__ spiked,
        const float* __restrict__ tau_theta,
        const float* __restrict__ tau_s,
        float* __restrict__ out)
{
    __shared__ int   s_cand[CHUNK];
    __shared__ float s_eps[CHUNK];
    __shared__ int   s_n;

    int tid = threadIdx.x;
    int row = blockIdx.x * NT + tid;

    float acc = 0.0f;
    const float* wrow = w + (size_t)row * NN;

    #pragma unroll 1
    for (int base = 0; base < NN; base += CHUNK) {
        if (tid == 0) s_n = 0;
        __syncthreads();

        // Screen columns [base, base+CHUNK): certain-zero iff tau_s>0 and
        // t >= 110*tau_s (expf(-t/tau_s) underflows to exactly +0 in fp32).
        for (int ccol = base + tid; ccol < base + CHUNK; ccol += NT) {
            float t    = ts[ccol] - 1.0f;
            float taus = tau_s[ccol];
            bool certain_zero = (taus > 0.0f) && (t >= 110.0f * taus);
            if (!certain_zero) {
                float eps = (1.0f + tanhf(t)) * expf(-t / taus) / taus;
                if (eps != 0.0f) {
                    int p = atomicAdd(&s_n, 1);
                    s_cand[p] = ccol;
                    s_eps[p]  = eps;
                }
            }
        }
        __syncthreads();

        int n = s_n;
        for (int j = 0; j < n; j++) {          // broadcast reads from shared
            int col  = s_cand[j];
            float we = (col == row) ? 0.0f : wrow[col];  // mask self-recurrence
            acc += we * s_eps[j];
        }
        __syncthreads();                        // protect s_n/s_cand for next chunk
    }

    // ---- epilogue (all loads coalesced, thread-per-row) ----
    float th = theta_v[row]
             + (theta_inf[row] - theta_v[row] + J_theta[row] * spiked[row]) / tau_theta[row];

    float vi     = v[row];
    float v_next = vi + (E_L[row] - vi + I_ext[row]) / tau_m[row] + acc;
    float notref = (ts[row] > 2.0f) ? 1.0f : 0.0f;
    float lam    = notref * c[row] * expf((v_next - th) / Delta_u[row]);
    lam = fminf(fmaxf(lam, 0.0f), 1.0f);

    // JAX uniform: bitcast((bits >> 9) | 0x3F800000) - 1.0 ; bernoulli = u < p
    uint32_t bits = threefry_bits_partitionable((uint32_t)row);
    float u  = __uint_as_float((bits >> 9) | 0x3F800000u) - 1.0f;
    float sp = (u < lam) ? 1.0f : 0.0f;

    out[row]          = lam;                   // spikes_lambda
    out[NN + row]     = sp;                    // spiked_new
    out[2 * NN + row] = (1.0f - sp) * v_next;  // v_new (reset potential = 0)
}

extern "C" void kernel_launch(void* const* d_in, const int* in_sizes, int n_in,
                              void* d_out, int out_size)
{
    const float* I_ext     = (const float*)d_in[0];
    const float* w         = (const float*)d_in[1];
    const float* v         = (const float*)d_in[2];
    const float* spiked    = (const float*)d_in[3];
    const float* ts        = (const float*)d_in[4];
    const float* theta_v   = (const float*)d_in[5];
    const float* tau_m     = (const float*)d_in[6];
    const float* tau_s     = (const float*)d_in[7];
    const float* tau_theta = (const float*)d_in[8];
    const float* J_theta   = (const float*)d_in[9];
    const float* E_L       = (const float*)d_in[10];
    const float* c         = (const float*)d_in[11];
    const float* Delta_u   = (const float*)d_in[12];
    const float* theta_inf = (const float*)d_in[13];
    float* out = (float*)d_out;

    k_fused<<<NB, NT>>>(w, v, I_ext, E_L, tau_m, ts, c, Delta_u,
                        theta_v, theta_inf, J_theta, spiked, tau_theta, tau_s, out);
}

// round 10
// speedup vs baseline: 1.4669x; 1.4669x over previous
#include <cuda_runtime.h>
#include <stdint.h>

#define NN 8192
#define PRE_BLOCKS 32
#define PRE_THREADS 256
#define MAIN_BLOCKS 64
#define MAIN_THREADS 128

// Scratch (device globals — no allocations). Reset-free: per-block segments
// overwritten by plain stores each launch.
__device__ int   g_idx[NN];         // compacted nonzero-eps indices, per-pre-block segments
__device__ float g_epsval[NN];      // compacted eps values, same segmentation
__device__ int   g_cnt[PRE_BLOCKS]; // per-block nonzero count (plain store each launch)

// Pre-pass: one column per thread (full MLP, no loops), per-block compaction.
__global__ void __launch_bounds__(PRE_THREADS) k_pre(const float* __restrict__ ts,
                                                     const float* __restrict__ tau_s)
{
    __shared__ int s_cnt;
    if (threadIdx.x == 0) s_cnt = 0;
    __syncthreads();

    int i = blockIdx.x * PRE_THREADS + threadIdx.x;

    // eps = (1 + tanh(t)) * exp(-t/tau_s) / tau_s,  t = ts - 1
    float t    = ts[i] - 1.0f;
    float taus = tau_s[i];
    float eps  = (1.0f + tanhf(t)) * expf(-t / taus) / taus;
    if (eps != 0.0f) {
        int p = atomicAdd(&s_cnt, 1);
        int base = blockIdx.x * PRE_THREADS;
        g_idx[base + p]    = i;
        g_epsval[base + p] = eps;
    }
    __syncthreads();
    if (threadIdx.x == 0) g_cnt[blockIdx.x] = s_cnt;   // overwrite; no reset kernel
}

// Threefry-2x32-20, key=(0,42), partitionable path: counter=(0, i), out = o1 ^ o2.
__device__ __forceinline__ uint32_t threefry_bits_partitionable(uint32_t i)
{
    const uint32_t ks0 = 0u;
    const uint32_t ks1 = 42u;
    const uint32_t ks2 = 0x1BD11BDAu ^ ks0 ^ ks1;
    uint32_t x0 = 0u + ks0;
    uint32_t x1 = i  + ks1;
    #define TF_RND(r) { x0 += x1; x1 = (x1 << (r)) | (x1 >> (32 - (r))); x1 ^= x0; }
    TF_RND(13) TF_RND(15) TF_RND(26) TF_RND(6)
    x0 += ks1; x1 += ks2 + 1u;
    TF_RND(17) TF_RND(29) TF_RND(16) TF_RND(24)
    x0 += ks2; x1 += ks0 + 2u;
    TF_RND(13) TF_RND(15) TF_RND(26) TF_RND(6)
    x0 += ks0; x1 += ks1 + 3u;
    TF_RND(17) TF_RND(29) TF_RND(16) TF_RND(24)
    x0 += ks1; x1 += ks2 + 4u;
    TF_RND(13) TF_RND(15) TF_RND(26) TF_RND(6)
    x0 += ks2; x1 += ks0 + 5u;
    #undef TF_RND
    return x0 ^ x1;
}

// Thread-per-row epilogue; gather only when some eps != 0.
__global__ void __launch_bounds__(MAIN_THREADS) k_main(
        const float* __restrict__ w,
        const float* __restrict__ v,
        const float* __restrict__ I_ext,
        const float* __restrict__ E_L,
        const float* __restrict__ tau_m,
        const float* __restrict__ ts,
        const float* __restrict__ c,
        const float* __restrict__ Delta_u,
        const float* __restrict__ theta_v,
        const float* __restrict__ theta_inf,
        const float* __restrict__ J_theta,
        const float* __restrict__ spiked,
        const float* __restrict__ tau_theta,
        float* __restrict__ out)
{
    __shared__ unsigned s_nzmask;

    int tid = threadIdx.x;
    int row = blockIdx.x * MAIN_THREADS + tid;

    // Warp 0: one coalesced read of the 32 segment counts -> nonzero mask.
    if (tid < 32) {
        int cnt = g_cnt[tid];
        unsigned m = __ballot_sync(0xFFFFFFFFu, cnt != 0);
        if (tid == 0) s_nzmask = m;
    }
    __syncthreads();

    float acc = 0.0f;
    unsigned nzm = s_nzmask;
    if (nzm) {
        // General sparse path (exact; cold in the nnz==0 regime).
        const float* wrow = w + (size_t)row * NN;
        while (nzm) {
            int b = __ffs(nzm) - 1;
            nzm &= nzm - 1;
            int cnt  = g_cnt[b];               // L2-broadcast across threads
            int base = b * PRE_THREADS;
            for (int j = 0; j < cnt; j++) {
                int col  = g_idx[base + j];
                float we = (col == row) ? 0.0f : wrow[col];  // mask self-recurrence
                acc += we * g_epsval[base + j];
            }
        }
    }

    // ---- fully coalesced elementwise epilogue ----
    float th = theta_v[row]
             + (theta_inf[row] - theta_v[row] + J_theta[row] * spiked[row]) / tau_theta[row];

    float vi     = v[row];
    float v_next = vi + (E_L[row] - vi + I_ext[row]) / tau_m[row] + acc;
    float notref = (ts[row] > 2.0f) ? 1.0f : 0.0f;
    float lam    = notref * c[row] * expf((v_next - th) / Delta_u[row]);
    lam = fminf(fmaxf(lam, 0.0f), 1.0f);

    // JAX uniform: bitcast((bits >> 9) | 0x3F800000) - 1.0 ; bernoulli = u < p
    uint32_t bits = threefry_bits_partitionable((uint32_t)row);
    float u  = __uint_as_float((bits >> 9) | 0x3F800000u) - 1.0f;
    float sp = (u < lam) ? 1.0f : 0.0f;

    out[row]          = lam;                   // spikes_lambda
    out[NN + row]     = sp;                    // spiked_new
    out[2 * NN + row] = (1.0f - sp) * v_next;  // v_new (reset potential = 0)
}

extern "C" void kernel_launch(void* const* d_in, const int* in_sizes, int n_in,
                              void* d_out, int out_size)
{
    const float* I_ext     = (const float*)d_in[0];
    const float* w         = (const float*)d_in[1];
    const float* v         = (const float*)d_in[2];
    const float* spiked    = (const float*)d_in[3];
    const float* ts        = (const float*)d_in[4];
    const float* theta_v   = (const float*)d_in[5];
    const float* tau_m     = (const float*)d_in[6];
    const float* tau_s     = (const float*)d_in[7];
    const float* tau_theta = (const float*)d_in[8];
    const float* J_theta   = (const float*)d_in[9];
    const float* E_L       = (const float*)d_in[10];
    const float* c         = (const float*)d_in[11];
    const float* Delta_u   = (const float*)d_in[12];
    const float* theta_inf = (const float*)d_in[13];
    float* out = (float*)d_out;

    k_pre<<<PRE_BLOCKS, PRE_THREADS>>>(ts, tau_s);
    k_main<<<MAIN_BLOCKS, MAIN_THREADS>>>(w, v, I_ext, E_L, tau_m, ts, c, Delta_u,
                                          theta_v, theta_inf, J_theta, spiked, tau_theta, out);
}